// round 4
// baseline (speedup 1.0000x reference)
#include <cuda_runtime.h>
#include <cstdint>

#define DEV_INLINE __device__ __forceinline__

// Problem constants
constexpr int B_ = 32, N_ = 400, T_ = 315, D_ = 512, H_ = 256;
constexpr int NT_ = N_ * T_;     // 126000
constexpr int ITERS = 100;

// ---- scratch (device globals; no runtime allocation allowed) ----
__device__ float g_tA[T_ * D_];          // text @ A^T            [315,512]
__device__ float g_s[B_ * N_ * T_];      // affinity scores        [32,400,315]
__device__ float g_mean[B_], g_rstd[B_];
__device__ float g_s1T[B_ * T_ * N_];    // sinkhorn result, transposed [b][t][n]
__device__ float g_f1[B_ * T_ * D_];     // features1              [32,315,512]
__device__ float g_txt[T_ * H_];         // text @ Wh_bot + bh     [315,256]
__device__ float g_h[B_ * T_ * H_];      // hidden (post relu)     [10080,256]

static inline int cdiv(int a, int b) { return (a + b - 1) / b; }

// ===================== generic fp32 GEMM =====================
// C[M,N] = X[M,K] * op(Y),  TB=1: Y is [N,K] (NT, C=X*Y^T); TB=0: Y is [K,N] (NN)
// EPI: 0 = none; 1 = +aux[col] (row-bias); 2 = relu(acc + aux[(row%T_)*H_ + col])
// K must be a multiple of 8. blockIdx.z batches with strides sX/sY/sC.
template<int TB, int EPI>
__global__ void __launch_bounds__(256) gemm_kernel(
    const float* __restrict__ X, const float* __restrict__ Y, float* __restrict__ C,
    int M, int N, int K, int ldx, int ldy, int ldc,
    long sX, long sY, long sC,
    const float* __restrict__ aux)
{
    X += (long)blockIdx.z * sX;
    Y += (long)blockIdx.z * sY;
    C += (long)blockIdx.z * sC;

    __shared__ float As[8][132];   // [k][m], padded stride for conflict-free access
    __shared__ float Bs[8][68];    // [k][n]

    const int tid = threadIdx.x;
    const int w = tid >> 5, l = tid & 31;
    const int row_t = (l >> 3) + (w >> 1) * 4;   // 0..15
    const int col_t = (l & 7) + (w & 1) * 8;     // 0..15
    const int rowBase = blockIdx.x * 128;
    const int colBase = blockIdx.y * 64;

    float acc[8][4];
#pragma unroll
    for (int i = 0; i < 8; i++)
#pragma unroll
        for (int j = 0; j < 4; j++) acc[i][j] = 0.f;

    const int xr = tid >> 1;            // 0..127
    const int xk = (tid & 1) * 4;       // 0 or 4
    const int grow = rowBase + xr;
    const int yn_nt = tid >> 2;         // 0..63
    const int yk_nt = (tid & 3) * 2;    // 0,2,4,6
    const int yk_nn = tid >> 5;         // 0..7
    const int yn_nn = (tid & 31) * 2;   // 0..62

    for (int k0 = 0; k0 < K; k0 += 8) {
        float4 xa = make_float4(0.f, 0.f, 0.f, 0.f);
        if (grow < M) xa = *(const float4*)(X + (long)grow * ldx + k0 + xk);
        float2 yb = make_float2(0.f, 0.f);
        if (TB) {
            int gn = colBase + yn_nt;
            if (gn < N) yb = *(const float2*)(Y + (long)gn * ldy + k0 + yk_nt);
        } else {
            int gn = colBase + yn_nn;
            if (gn < N) yb = *(const float2*)(Y + (long)(k0 + yk_nn) * ldy + gn);
        }
        __syncthreads();
        As[xk + 0][xr] = xa.x; As[xk + 1][xr] = xa.y;
        As[xk + 2][xr] = xa.z; As[xk + 3][xr] = xa.w;
        if (TB) { Bs[yk_nt][yn_nt] = yb.x; Bs[yk_nt + 1][yn_nt] = yb.y; }
        else    { Bs[yk_nn][yn_nn] = yb.x; Bs[yk_nn][yn_nn + 1] = yb.y; }
        __syncthreads();

#pragma unroll
        for (int kk = 0; kk < 8; kk++) {
            float4 a0 = *(const float4*)&As[kk][row_t * 8];
            float4 a1 = *(const float4*)&As[kk][row_t * 8 + 4];
            float4 bb = *(const float4*)&Bs[kk][col_t * 4];
            float a[8] = {a0.x, a0.y, a0.z, a0.w, a1.x, a1.y, a1.z, a1.w};
            float bv[4] = {bb.x, bb.y, bb.z, bb.w};
#pragma unroll
            for (int i = 0; i < 8; i++)
#pragma unroll
                for (int j = 0; j < 4; j++)
                    acc[i][j] += a[i] * bv[j];
        }
    }

#pragma unroll
    for (int i = 0; i < 8; i++) {
        int rr = rowBase + row_t * 8 + i;
        if (rr >= M) continue;
#pragma unroll
        for (int j = 0; j < 4; j++) {
            int cc = colBase + col_t * 4 + j;
            if (cc >= N) continue;
            float v = acc[i][j];
            if (EPI == 1) v += aux[cc];
            if (EPI == 2) { v += aux[(long)(rr % T_) * H_ + cc]; v = fmaxf(v, 0.f); }
            C[(long)rr * ldc + cc] = v;
        }
    }
}

// ===================== per-batch mean / rstd =====================
__global__ void __launch_bounds__(256) stats_kernel(const float* __restrict__ s,
                                                    float* __restrict__ mean,
                                                    float* __restrict__ rstd)
{
    const int b = blockIdx.x;
    const float* p = s + (long)b * NT_;
    float sum = 0.f, sq = 0.f;
    for (int i = threadIdx.x; i < NT_; i += 256) {
        float x = p[i];
        sum += x; sq += x * x;
    }
#pragma unroll
    for (int o = 16; o > 0; o >>= 1) {
        sum += __shfl_xor_sync(0xffffffffu, sum, o);
        sq  += __shfl_xor_sync(0xffffffffu, sq, o);
    }
    __shared__ float s1[8], s2[8];
    int w = threadIdx.x >> 5, l = threadIdx.x & 31;
    if (l == 0) { s1[w] = sum; s2[w] = sq; }
    __syncthreads();
    if (threadIdx.x == 0) {
        float S = 0.f, Q = 0.f;
        for (int i = 0; i < 8; i++) { S += s1[i]; Q += s2[i]; }
        float m = S / (float)NT_;
        float var = Q / (float)NT_ - m * m;
        mean[b] = m;
        rstd[b] = rsqrtf(var + 1e-5f);
    }
}

// ===================== sinkhorn (scaling-vector form) =====================
// Cluster of 4 CTAs per batch element; CTA r owns rows [r*100, r*100+100).
// M = exp(instnorm(s)) lives in SMEM (row stride 321 for conflict-free
// transposed reads). Iterate u = 1/(M v), v = 1/(M^T u) 100x; write
// s1^T[b][t][n] = M[n][t]*u[n]*v[t].
//
// Cross-CTA column partials use PING-PONG buffers (vpart[2][320]) so only ONE
// barrier.cluster per iteration is needed: a CTA's arrival at iteration i+1's
// sync happens-after its reads of buffer (i&1), and that buffer is only
// overwritten in iteration i+2 (after that sync) — WAR closed by one barrier.
constexpr int ROWS_PER_CTA = 100;
constexpr int TP = 320;           // padded T (zeros in 315..319)
constexpr int MSTRIDE = 321;      // odd stride -> conflict-free column reads
constexpr int SINK_SMEM_FLOATS =
    ROWS_PER_CTA * MSTRIDE /*Ms*/ + 104 /*u*/ + TP /*v*/ + 2 * TP /*vpart pp*/ + 8 * TP /*vw*/;
constexpr int SINK_SMEM = SINK_SMEM_FLOATS * 4;

DEV_INLINE uint32_t smem_u32(const void* p) {
    uint32_t a;
    asm("{ .reg .u64 t; cvta.to.shared.u64 t, %1; cvt.u32.u64 %0, t; }"
        : "=r"(a) : "l"(p));
    return a;
}
DEV_INLINE float dsmem_ld_f32(uint32_t local_addr, uint32_t rank) {
    uint32_t ra; float v;
    asm volatile("mapa.shared::cluster.u32 %0, %1, %2;" : "=r"(ra) : "r"(local_addr), "r"(rank));
    asm volatile("ld.shared::cluster.f32 %0, [%1];" : "=f"(v) : "r"(ra) : "memory");
    return v;
}
DEV_INLINE void cluster_sync() {
    asm volatile("barrier.cluster.arrive.aligned;" ::: "memory");
    asm volatile("barrier.cluster.wait.aligned;" ::: "memory");
}

__global__ void __cluster_dims__(4, 1, 1) __launch_bounds__(256, 1)
sinkhorn_kernel(const float* __restrict__ s,
                const float* __restrict__ mean, const float* __restrict__ rstd,
                const float* __restrict__ gamma, const float* __restrict__ beta,
                float* __restrict__ s1T)
{
    extern __shared__ float sm[];
    float* Ms    = sm;                               // [100][321]
    float* u_s   = Ms + ROWS_PER_CTA * MSTRIDE;      // [104]
    float* v     = u_s + 104;                        // [320]
    float* vpart = v + TP;                           // [2][320] ping-pong col partials
    float* vw    = vpart + 2 * TP;                   // [8][320] per-warp partials

    const int tid = threadIdx.x;
    const int w = tid >> 5, l = tid & 31;
    uint32_t rank; asm("mov.u32 %0, %%cluster_ctarank;" : "=r"(rank));
    const int b = blockIdx.x >> 2;
    const int r = (int)rank;

    const float scale = gamma[0] * rstd[b];
    const float shift = beta[0] - scale * mean[b];
    const float* srow = s + ((long)b * N_ + (long)r * ROWS_PER_CTA) * T_;

    // load + instance-norm + exp (exp(x) = exp2(x*log2 e))
    for (int idx = tid; idx < ROWS_PER_CTA * T_; idx += 256) {
        int n = idx / T_, t = idx - n * T_;
        float x = srow[idx];
        Ms[n * MSTRIDE + t] = exp2f((x * scale + shift) * 1.4426950408889634f);
    }
    for (int idx = tid; idx < ROWS_PER_CTA * 6; idx += 256) {
        int n = idx / 6;
        Ms[n * MSTRIDE + T_ + (idx % 6)] = 0.f;   // zero pad cols 315..320
    }
    for (int t = tid; t < TP; t += 256) v[t] = (t < T_) ? 1.f : 0.f;
    __syncthreads();

    const uint32_t vpart_addr = smem_u32(vpart);

    for (int it = 0; it < ITERS; ++it) {
        float* vp_cur = vpart + (it & 1) * TP;
        const uint32_t vp_cur_off = vpart_addr + (uint32_t)((it & 1) * TP * 4);

        // ---- fused row pass: u[n] and per-warp col partials ----
        float vv[10], vp[10];
#pragma unroll
        for (int j = 0; j < 10; j++) { vv[j] = v[l + 32 * j]; vp[j] = 0.f; }

        for (int n = w; n < ROWS_PER_CTA; n += 8) {
            float m0[10];
            float sum = 0.f;
            const float* mrow = Ms + n * MSTRIDE + l;
#pragma unroll
            for (int j = 0; j < 10; j++) { m0[j] = mrow[32 * j]; sum += m0[j] * vv[j]; }
#pragma unroll
            for (int o = 16; o > 0; o >>= 1) sum += __shfl_xor_sync(0xffffffffu, sum, o);
            float un = __fdividef(1.f, sum);
            if (l == 0) u_s[n] = un;
#pragma unroll
            for (int j = 0; j < 10; j++) vp[j] += m0[j] * un;
        }
#pragma unroll
        for (int j = 0; j < 10; j++) vw[w * TP + l + 32 * j] = vp[j];
        __syncthreads();

        // combine 8 warps -> vpart[cur] (deterministic order)
        for (int t = tid; t < TP; t += 256) {
            float a = 0.f;
#pragma unroll
            for (int ww = 0; ww < 8; ww++) a += vw[ww * TP + t];
            vp_cur[t] = a;
        }
        cluster_sync();   // all CTAs' vpart[cur] visible (single sync per iter)

        // combine 4 CTAs via DSMEM -> v
        for (int t = tid; t < TP; t += 256) {
            float a = 0.f;
#pragma unroll
            for (uint32_t rr = 0; rr < 4; rr++) a += dsmem_ld_f32(vp_cur_off + t * 4, rr);
            v[t] = (t < T_) ? __fdividef(1.f, a) : 0.f;
        }
        __syncthreads();  // v fully written before next row pass reads it
    }

    // write s1^T: [b][t][n], coalesced along n
    float* outb = s1T + (long)b * T_ * N_;
    for (int t = w; t < T_; t += 8) {
        float vt = v[t];
#pragma unroll
        for (int k = 0; k < 4; k++) {
            int n = l + 32 * k;
            if (n < ROWS_PER_CTA)
                outb[(long)t * N_ + r * ROWS_PER_CTA + n] = Ms[n * MSTRIDE + t] * u_s[n] * vt;
        }
    }
}

// ===================== final: pred = h @ Wo + bo =====================
__global__ void __launch_bounds__(256) pred_kernel(const float* __restrict__ h,
                                                   const float* __restrict__ Wo,
                                                   const float* __restrict__ bo,
                                                   float* __restrict__ out)
{
    int w = threadIdx.x >> 5, l = threadIdx.x & 31;
    int m = blockIdx.x * 8 + w;
    if (m >= B_ * T_) return;
    const float* hp = h + (long)m * H_;
    float sum = 0.f;
#pragma unroll
    for (int j = 0; j < 8; j++) sum += hp[l + 32 * j] * Wo[l + 32 * j];
#pragma unroll
    for (int o = 16; o > 0; o >>= 1) sum += __shfl_xor_sync(0xffffffffu, sum, o);
    if (l == 0) out[m] = sum + bo[0];
}

// ===================== launch =====================
extern "C" void kernel_launch(void* const* d_in, const int* in_sizes, int n_in,
                              void* d_out, int out_size)
{
    const float* features = (const float*)d_in[0];  // [32,400,512]
    const float* text     = (const float*)d_in[1];  // [315,512]
    const float* A        = (const float*)d_in[2];  // [512,512]
    const float* gamma    = (const float*)d_in[3];
    const float* beta     = (const float*)d_in[4];
    const float* Wh       = (const float*)d_in[5];  // [1024,256]
    const float* bh       = (const float*)d_in[6];  // [256]
    const float* Wo       = (const float*)d_in[7];  // [256,1]
    const float* bo       = (const float*)d_in[8];  // [1]
    float* out = (float*)d_out;                     // [32,315]

    float *tA, *s, *mean, *rstd, *s1T, *f1, *txt, *h;
    cudaGetSymbolAddress((void**)&tA,   g_tA);
    cudaGetSymbolAddress((void**)&s,    g_s);
    cudaGetSymbolAddress((void**)&mean, g_mean);
    cudaGetSymbolAddress((void**)&rstd, g_rstd);
    cudaGetSymbolAddress((void**)&s1T,  g_s1T);
    cudaGetSymbolAddress((void**)&f1,   g_f1);
    cudaGetSymbolAddress((void**)&txt,  g_txt);
    cudaGetSymbolAddress((void**)&h,    g_h);

    dim3 thr(256);

    // tA[t,d] = sum_e text[t,e] * A[d,e]     (NT)
    gemm_kernel<1, 0><<<dim3(cdiv(T_, 128), D_ / 64, 1), thr>>>(
        text, A, tA, T_, D_, D_, D_, D_, D_, 0, 0, 0, nullptr);

    // s[b*400+n, t] = sum_d f[.,d] * tA[t,d]  (NT)
    gemm_kernel<1, 0><<<dim3((B_ * N_) / 128, cdiv(T_, 64), 1), thr>>>(
        features, tA, s, B_ * N_, T_, D_, D_, D_, T_, 0, 0, 0, nullptr);

    // per-batch mean / rstd
    stats_kernel<<<B_, 256>>>(s, mean, rstd);

    // sinkhorn (4-CTA clusters, one cluster per batch)
    cudaFuncSetAttribute(sinkhorn_kernel, cudaFuncAttributeMaxDynamicSharedMemorySize, SINK_SMEM);
    sinkhorn_kernel<<<B_ * 4, 256, SINK_SMEM>>>(s, mean, rstd, gamma, beta, s1T);

    // f1[b][t,d] = sum_n s1T[b][t,n] * f[b][n,d]   (NN, batched)
    gemm_kernel<0, 0><<<dim3(cdiv(T_, 128), D_ / 64, B_), thr>>>(
        s1T, features, f1, T_, D_, N_, N_, D_, D_,
        (long)T_ * N_, (long)N_ * D_, (long)T_ * D_, nullptr);

    // txt[t,h] = sum_e text[t,e] * Wh[512+e,h] + bh[h]   (NN, bias epilogue)
    gemm_kernel<0, 1><<<dim3(cdiv(T_, 128), H_ / 64, 1), thr>>>(
        text, Wh + (size_t)D_ * H_, txt, T_, H_, D_, D_, H_, H_, 0, 0, 0, bh);

    // h[m,j] = relu(sum_d f1[m,d]*Wh[d,j] + txt[m%315, j])   (NN, fused epilogue)
    gemm_kernel<0, 2><<<dim3(cdiv(B_ * T_, 128), H_ / 64, 1), thr>>>(
        f1, Wh, h, B_ * T_, H_, D_, D_, H_, H_, 0, 0, 0, txt);

    // pred[m] = h[m,:] @ Wo + bo
    pred_kernel<<<cdiv(B_ * T_, 8), 256>>>(h, Wo, bo, out);
}

// round 6
// speedup vs baseline: 1.2636x; 1.2636x over previous
#include <cuda_runtime.h>
#include <cstdint>

#define DEV_INLINE __device__ __forceinline__

// Problem constants
constexpr int B_ = 32, N_ = 400, T_ = 315, D_ = 512, H_ = 256;
constexpr int NT_ = N_ * T_;     // 126000
constexpr int ITERS = 100;

// ---- scratch (device globals; no runtime allocation allowed) ----
__device__ float g_tA[T_ * D_];          // text @ A^T            [315,512]
__device__ float g_s[B_ * N_ * T_];      // affinity scores        [32,400,315]
__device__ float g_mean[B_], g_rstd[B_];
__device__ float g_s1T[B_ * T_ * N_];    // sinkhorn result, transposed [b][t][n]
__device__ float g_f1[B_ * T_ * D_];     // features1              [32,315,512]
__device__ float g_txt[T_ * H_];         // text @ Wh_bot + bh     [315,256]
__device__ float g_h[B_ * T_ * H_];      // hidden (post relu)     [10080,256]

static inline int cdiv(int a, int b) { return (a + b - 1) / b; }

// ===================== generic fp32 GEMM =====================
// C[M,N] = X[M,K] * op(Y),  TB=1: Y is [N,K] (NT, C=X*Y^T); TB=0: Y is [K,N] (NN)
// EPI: 0 = none; 1 = +aux[col] (row-bias); 2 = relu(acc + aux[(row%T_)*H_ + col])
template<int TB, int EPI>
__global__ void __launch_bounds__(256) gemm_kernel(
    const float* __restrict__ X, const float* __restrict__ Y, float* __restrict__ C,
    int M, int N, int K, int ldx, int ldy, int ldc,
    long sX, long sY, long sC,
    const float* __restrict__ aux)
{
    X += (long)blockIdx.z * sX;
    Y += (long)blockIdx.z * sY;
    C += (long)blockIdx.z * sC;

    __shared__ float As[8][132];
    __shared__ float Bs[8][68];

    const int tid = threadIdx.x;
    const int w = tid >> 5, l = tid & 31;
    const int row_t = (l >> 3) + (w >> 1) * 4;   // 0..15
    const int col_t = (l & 7) + (w & 1) * 8;     // 0..15
    const int rowBase = blockIdx.x * 128;
    const int colBase = blockIdx.y * 64;

    float acc[8][4];
#pragma unroll
    for (int i = 0; i < 8; i++)
#pragma unroll
        for (int j = 0; j < 4; j++) acc[i][j] = 0.f;

    const int xr = tid >> 1;
    const int xk = (tid & 1) * 4;
    const int grow = rowBase + xr;
    const int yn_nt = tid >> 2;
    const int yk_nt = (tid & 3) * 2;
    const int yk_nn = tid >> 5;
    const int yn_nn = (tid & 31) * 2;

    for (int k0 = 0; k0 < K; k0 += 8) {
        float4 xa = make_float4(0.f, 0.f, 0.f, 0.f);
        if (grow < M) xa = *(const float4*)(X + (long)grow * ldx + k0 + xk);
        float2 yb = make_float2(0.f, 0.f);
        if (TB) {
            int gn = colBase + yn_nt;
            if (gn < N) yb = *(const float2*)(Y + (long)gn * ldy + k0 + yk_nt);
        } else {
            int gn = colBase + yn_nn;
            if (gn < N) yb = *(const float2*)(Y + (long)(k0 + yk_nn) * ldy + gn);
        }
        __syncthreads();
        As[xk + 0][xr] = xa.x; As[xk + 1][xr] = xa.y;
        As[xk + 2][xr] = xa.z; As[xk + 3][xr] = xa.w;
        if (TB) { Bs[yk_nt][yn_nt] = yb.x; Bs[yk_nt + 1][yn_nt] = yb.y; }
        else    { Bs[yk_nn][yn_nn] = yb.x; Bs[yk_nn][yn_nn + 1] = yb.y; }
        __syncthreads();

#pragma unroll
        for (int kk = 0; kk < 8; kk++) {
            float4 a0 = *(const float4*)&As[kk][row_t * 8];
            float4 a1 = *(const float4*)&As[kk][row_t * 8 + 4];
            float4 bb = *(const float4*)&Bs[kk][col_t * 4];
            float a[8] = {a0.x, a0.y, a0.z, a0.w, a1.x, a1.y, a1.z, a1.w};
            float bv[4] = {bb.x, bb.y, bb.z, bb.w};
#pragma unroll
            for (int i = 0; i < 8; i++)
#pragma unroll
                for (int j = 0; j < 4; j++)
                    acc[i][j] += a[i] * bv[j];
        }
    }

#pragma unroll
    for (int i = 0; i < 8; i++) {
        int rr = rowBase + row_t * 8 + i;
        if (rr >= M) continue;
#pragma unroll
        for (int j = 0; j < 4; j++) {
            int cc = colBase + col_t * 4 + j;
            if (cc >= N) continue;
            float v = acc[i][j];
            if (EPI == 1) v += aux[cc];
            if (EPI == 2) { v += aux[(long)(rr % T_) * H_ + cc]; v = fmaxf(v, 0.f); }
            C[(long)rr * ldc + cc] = v;
        }
    }
}

// ===================== per-batch mean / rstd =====================
__global__ void __launch_bounds__(256) stats_kernel(const float* __restrict__ s,
                                                    float* __restrict__ mean,
                                                    float* __restrict__ rstd)
{
    const int b = blockIdx.x;
    const float* p = s + (long)b * NT_;
    float sum = 0.f, sq = 0.f;
    for (int i = threadIdx.x; i < NT_; i += 256) {
        float x = p[i];
        sum += x; sq += x * x;
    }
#pragma unroll
    for (int o = 16; o > 0; o >>= 1) {
        sum += __shfl_xor_sync(0xffffffffu, sum, o);
        sq  += __shfl_xor_sync(0xffffffffu, sq, o);
    }
    __shared__ float s1[8], s2[8];
    int w = threadIdx.x >> 5, l = threadIdx.x & 31;
    if (l == 0) { s1[w] = sum; s2[w] = sq; }
    __syncthreads();
    if (threadIdx.x == 0) {
        float S = 0.f, Q = 0.f;
        for (int i = 0; i < 8; i++) { S += s1[i]; Q += s2[i]; }
        float m = S / (float)NT_;
        float var = Q / (float)NT_ - m * m;
        mean[b] = m;
        rstd[b] = rsqrtf(var + 1e-5f);
    }
}

// ===================== sinkhorn (register-resident M) =====================
// Cluster of 4 CTAs per batch element; CTA r owns rows [r*100, r*100+100).
// 640 threads = 20 warps; warp w owns rows {w, w+20, w+40, w+60, w+80}. Each
// thread keeps its 5x10 M-values IN REGISTERS for all 100 iterations (lane l
// holds columns t = l+32j). Reg budget: 65536/640 = 102/thread — 50 (M) + 20
// (vv/vp) + ~20 misc fits without spills. Smem keeps one copy of M only for
// the coalesced epilogue. Iterate u = 1/(M v), v = 1/(M^T u); s1^T = M*(u x v).
// Single cluster barrier per iteration via ping-pong vpart buffers.
constexpr int ROWS_PER_CTA = 100;
constexpr int TP = 320;             // padded T (zeros at 315..319)
constexpr int MSTRIDE = 321;        // conflict-free column reads in epilogue
constexpr int SINK_THREADS = 640;   // 20 warps
constexpr int SINK_WARPS = 20;
constexpr int ROWS_PER_THREAD = 5;  // 100 / 20
constexpr int SINK_SMEM_FLOATS =
    ROWS_PER_CTA * MSTRIDE /*Ms*/ + 104 /*u*/ + TP /*v*/ + 2 * TP /*vpart pp*/
    + SINK_WARPS * TP /*vw*/;
constexpr int SINK_SMEM = SINK_SMEM_FLOATS * 4;   // 158,256 B

DEV_INLINE uint32_t smem_u32(const void* p) {
    uint32_t a;
    asm("{ .reg .u64 t; cvta.to.shared.u64 t, %1; cvt.u32.u64 %0, t; }"
        : "=r"(a) : "l"(p));
    return a;
}
DEV_INLINE float dsmem_ld_f32(uint32_t local_addr, uint32_t rank) {
    uint32_t ra; float v;
    asm volatile("mapa.shared::cluster.u32 %0, %1, %2;" : "=r"(ra) : "r"(local_addr), "r"(rank));
    asm volatile("ld.shared::cluster.f32 %0, [%1];" : "=f"(v) : "r"(ra) : "memory");
    return v;
}
DEV_INLINE void cluster_sync() {
    asm volatile("barrier.cluster.arrive.aligned;" ::: "memory");
    asm volatile("barrier.cluster.wait.aligned;" ::: "memory");
}

__global__ void __cluster_dims__(4, 1, 1) __launch_bounds__(SINK_THREADS, 1)
sinkhorn_kernel(const float* __restrict__ s,
                const float* __restrict__ mean, const float* __restrict__ rstd,
                const float* __restrict__ gamma, const float* __restrict__ beta,
                float* __restrict__ s1T)
{
    extern __shared__ float sm[];
    float* Ms    = sm;                               // [100][321] (epilogue only)
    float* u_s   = Ms + ROWS_PER_CTA * MSTRIDE;      // [104] (written last iter)
    float* v     = u_s + 104;                        // [320]
    float* vpart = v + TP;                           // [2][320] ping-pong
    float* vw    = vpart + 2 * TP;                   // [20][320] per-warp partials

    const int tid = threadIdx.x;
    const int w = tid >> 5, l = tid & 31;
    uint32_t rank; asm("mov.u32 %0, %%cluster_ctarank;" : "=r"(rank));
    const int b = blockIdx.x >> 2;
    const int r = (int)rank;

    const float scale = gamma[0] * rstd[b];
    const float shift = beta[0] - scale * mean[b];
    const float* srow = s + ((long)b * N_ + (long)r * ROWS_PER_CTA) * T_;

    // ---- init: load s, instance-norm, exp -> registers AND epilogue smem copy
    float m[ROWS_PER_THREAD][10];
#pragma unroll
    for (int k = 0; k < ROWS_PER_THREAD; k++) {
        int n = w + SINK_WARPS * k;                  // 0..99
#pragma unroll
        for (int j = 0; j < 10; j++) {
            int t = l + 32 * j;                      // 0..319
            float mm = 0.f;
            if (t < T_) {
                float x = srow[(long)n * T_ + t];
                mm = exp2f((x * scale + shift) * 1.4426950408889634f);
            }
            m[k][j] = mm;
            Ms[n * MSTRIDE + t] = mm;                // pad cols get 0
        }
    }
    for (int t = tid; t < TP; t += SINK_THREADS) v[t] = (t < T_) ? 1.f : 0.f;
    __syncthreads();

    const uint32_t vpart_addr = smem_u32(vpart);

    for (int it = 0; it < ITERS; ++it) {
        float* vp_cur = vpart + (it & 1) * TP;
        const uint32_t vp_cur_off = vpart_addr + (uint32_t)((it & 1) * TP * 4);

        // ---- fused row pass (M from registers): u[n] + per-warp col partials
        float vv[10], vp[10];
#pragma unroll
        for (int j = 0; j < 10; j++) { vv[j] = v[l + 32 * j]; vp[j] = 0.f; }

#pragma unroll
        for (int k = 0; k < ROWS_PER_THREAD; k++) {
            float sum = 0.f;
#pragma unroll
            for (int j = 0; j < 10; j++) sum += m[k][j] * vv[j];
#pragma unroll
            for (int o = 16; o > 0; o >>= 1) sum += __shfl_xor_sync(0xffffffffu, sum, o);
            float un = __fdividef(1.f, sum);
            if (it == ITERS - 1 && l == 0) u_s[w + SINK_WARPS * k] = un;
#pragma unroll
            for (int j = 0; j < 10; j++) vp[j] += m[k][j] * un;
        }
#pragma unroll
        for (int j = 0; j < 10; j++) vw[w * TP + l + 32 * j] = vp[j];
        __syncthreads();

        // combine 20 warps -> vpart[cur] (deterministic order)
        for (int t = tid; t < TP; t += SINK_THREADS) {
            float a = 0.f;
#pragma unroll
            for (int ww = 0; ww < SINK_WARPS; ww++) a += vw[ww * TP + t];
            vp_cur[t] = a;
        }
        cluster_sync();   // all CTAs' vpart[cur] visible (single sync per iter)

        // combine 4 CTAs via DSMEM -> v
        for (int t = tid; t < TP; t += SINK_THREADS) {
            float a = 0.f;
#pragma unroll
            for (uint32_t rr = 0; rr < 4; rr++) a += dsmem_ld_f32(vp_cur_off + t * 4, rr);
            v[t] = (t < T_) ? __fdividef(1.f, a) : 0.f;
        }
        __syncthreads();  // v fully written before next row pass reads it
    }

    // ---- epilogue: s1^T[b][t][n], coalesced along n (via smem M copy)
    float* outb = s1T + (long)b * T_ * N_;
    for (int t = w; t < T_; t += SINK_WARPS) {
        float vt = v[t];
#pragma unroll
        for (int k = 0; k < 4; k++) {
            int n = l + 32 * k;
            if (n < ROWS_PER_CTA)
                outb[(long)t * N_ + r * ROWS_PER_CTA + n] = Ms[n * MSTRIDE + t] * u_s[n] * vt;
        }
    }
}

// ===================== final: pred = h @ Wo + bo =====================
__global__ void __launch_bounds__(256) pred_kernel(const float* __restrict__ h,
                                                   const float* __restrict__ Wo,
                                                   const float* __restrict__ bo,
                                                   float* __restrict__ out)
{
    int w = threadIdx.x >> 5, l = threadIdx.x & 31;
    int m = blockIdx.x * 8 + w;
    if (m >= B_ * T_) return;
    const float* hp = h + (long)m * H_;
    float sum = 0.f;
#pragma unroll
    for (int j = 0; j < 8; j++) sum += hp[l + 32 * j] * Wo[l + 32 * j];
#pragma unroll
    for (int o = 16; o > 0; o >>= 1) sum += __shfl_xor_sync(0xffffffffu, sum, o);
    if (l == 0) out[m] = sum + bo[0];
}

// ===================== launch =====================
extern "C" void kernel_launch(void* const* d_in, const int* in_sizes, int n_in,
                              void* d_out, int out_size)
{
    const float* features = (const float*)d_in[0];  // [32,400,512]
    const float* text     = (const float*)d_in[1];  // [315,512]
    const float* A        = (const float*)d_in[2];  // [512,512]
    const float* gamma    = (const float*)d_in[3];
    const float* beta     = (const float*)d_in[4];
    const float* Wh       = (const float*)d_in[5];  // [1024,256]
    const float* bh       = (const float*)d_in[6];  // [256]
    const float* Wo       = (const float*)d_in[7];  // [256,1]
    const float* bo       = (const float*)d_in[8];  // [1]
    float* out = (float*)d_out;                     // [32,315]

    float *tA, *s, *mean, *rstd, *s1T, *f1, *txt, *h;
    cudaGetSymbolAddress((void**)&tA,   g_tA);
    cudaGetSymbolAddress((void**)&s,    g_s);
    cudaGetSymbolAddress((void**)&mean, g_mean);
    cudaGetSymbolAddress((void**)&rstd, g_rstd);
    cudaGetSymbolAddress((void**)&s1T,  g_s1T);
    cudaGetSymbolAddress((void**)&f1,   g_f1);
    cudaGetSymbolAddress((void**)&txt,  g_txt);
    cudaGetSymbolAddress((void**)&h,    g_h);

    dim3 thr(256);

    // tA[t,d] = sum_e text[t,e] * A[d,e]     (NT)
    gemm_kernel<1, 0><<<dim3(cdiv(T_, 128), D_ / 64, 1), thr>>>(
        text, A, tA, T_, D_, D_, D_, D_, D_, 0, 0, 0, nullptr);

    // s[b*400+n, t] = sum_d f[.,d] * tA[t,d]  (NT)
    gemm_kernel<1, 0><<<dim3((B_ * N_) / 128, cdiv(T_, 64), 1), thr>>>(
        features, tA, s, B_ * N_, T_, D_, D_, D_, T_, 0, 0, 0, nullptr);

    // per-batch mean / rstd
    stats_kernel<<<B_, 256>>>(s, mean, rstd);

    // sinkhorn (4-CTA clusters, one cluster per batch; 640 threads)
    cudaFuncSetAttribute(sinkhorn_kernel, cudaFuncAttributeMaxDynamicSharedMemorySize, SINK_SMEM);
    sinkhorn_kernel<<<B_ * 4, SINK_THREADS, SINK_SMEM>>>(s, mean, rstd, gamma, beta, s1T);

    // f1[b][t,d] = sum_n s1T[b][t,n] * f[b][n,d]   (NN, batched)
    gemm_kernel<0, 0><<<dim3(cdiv(T_, 128), D_ / 64, B_), thr>>>(
        s1T, features, f1, T_, D_, N_, N_, D_, D_,
        (long)T_ * N_, (long)N_ * D_, (long)T_ * D_, nullptr);

    // txt[t,h] = sum_e text[t,e] * Wh[512+e,h] + bh[h]   (NN, bias epilogue)
    gemm_kernel<0, 1><<<dim3(cdiv(T_, 128), H_ / 64, 1), thr>>>(
        text, Wh + (size_t)D_ * H_, txt, T_, H_, D_, D_, H_, H_, 0, 0, 0, bh);

    // h[m,j] = relu(sum_d f1[m,d]*Wh[d,j] + txt[m%315, j])   (NN, fused epilogue)
    gemm_kernel<0, 2><<<dim3(cdiv(B_ * T_, 128), H_ / 64, 1), thr>>>(
        f1, Wh, h, B_ * T_, H_, D_, D_, H_, H_, 0, 0, 0, txt);

    // pred[m] = h[m,:] @ Wo + bo
    pred_kernel<<<cdiv(B_ * T_, 8), 256>>>(h, Wo, bo, out);
}